// round 11
// baseline (speedup 1.0000x reference)
#include <cuda_runtime.h>
#include <cuda_fp16.h>
#include <mma.h>
#include <math.h>

using namespace nvcuda;

#define NN   20000
#define NP   20096   // padded rows: 157*128
#define EE   320000
#define BBATCH 128
#define FIN  25
#define DIM  64
#define NH   8
#define F512 512   // NH*DIM

// ---------------- scratch (static device globals; zero-init, no allocation) ----
__device__ float   g_h0[NP * DIM];
__device__ __half  g_h0h[NP * DIM];
__device__ __half  g_Wgh[DIM * F512];
__device__ __half  g_Whh[F512 * DIM];
__device__ __half2 g_xh2[NP * (F512 / 2)];   // xh fp16
__device__ __half  g_aggh[NP * F512];        // agg fp16
__device__ float   g_P[DIM * 16];
__device__ float   g_as[NN * NH];
__device__ float   g_ad[NN * NH];
__device__ int     g_cnt[NN];
__device__ int     g_offs[NN + 1];
__device__ int     g_cursor[NN];
__device__ int     g_csr[EE];
__device__ float   g_out[NP * DIM];

__device__ __forceinline__ float lrelu(float x) { return x > 0.f ? x : 0.2f * x; }
__device__ __forceinline__ float sigmoidf_(float x) { return 1.f / (1.f + __expf(-x)); }

// ---------------- k_pre: fused cvtW (128 blk) + zero (79 blk) + patt (1 blk) ----
__global__ void k_pre(const float* __restrict__ Wg, const float* __restrict__ Wh,
                      const float* __restrict__ as_, const float* __restrict__ ad_) {
    int bid = blockIdx.x;
    int tid = threadIdx.x;
    if (bid < 128) {                       // cvtW: 32768 elems, 256/blk
        int i = bid * 256 + tid;
        g_Wgh[i] = __float2half(Wg[i]);
        g_Whh[i] = __float2half(Wh[i]);
    } else if (bid < 128 + 79) {           // zero cnt
        int i = (bid - 128) * 256 + tid;
        if (i < NN) g_cnt[i] = 0;
    } else {                               // patt: 1024 outputs, 4 per thread
#pragma unroll
        for (int u = 0; u < 4; u++) {
            int idx = tid * 4 + u;         // idx = k*16 + o
            int k = idx >> 4, o = idx & 15;
            int h = o & 7;
            const float* att = (o < 8) ? as_ : ad_;
            float s = 0.f;
#pragma unroll 8
            for (int c = 0; c < 64; c++)
                s = fmaf(Wg[k * F512 + h * 64 + c], att[h * 64 + c], s);
            g_P[idx] = s;
        }
    }
}

// ---------------- k1: h0 = relu(x @ W0 + b0) + fused a_s/a_d -------------------
__global__ void k_h0(const float* __restrict__ x, const float* __restrict__ W0,
                     const float* __restrict__ b0) {
    __shared__ float sW[FIN * DIM];
    __shared__ float sb[DIM];
    __shared__ float sx[4][FIN];
    __shared__ float sh0[4][DIM];
    __shared__ float sP[DIM * 16];
    int tid = threadIdx.x;
    for (int i = tid; i < FIN * DIM; i += 256) sW[i] = W0[i];
    for (int i = tid; i < DIM * 16; i += 256) sP[i] = g_P[i];
    if (tid < DIM) sb[tid] = b0[tid];
    int rb = blockIdx.x * 4;
    if (tid < 4 * FIN) {
        int row = rb + tid / FIN;
        sx[tid / FIN][tid % FIN] = (row < NN) ? x[(size_t)row * FIN + tid % FIN] : 0.f;
    }
    __syncthreads();
    int c = tid & 63, r = tid >> 6;
    float acc = sb[c];
#pragma unroll
    for (int k = 0; k < FIN; k++) acc = fmaf(sx[r][k], sW[k * DIM + c], acc);
    float v = fmaxf(acc, 0.f);
    g_h0[(size_t)(rb + r) * DIM + c] = v;
    g_h0h[(size_t)(rb + r) * DIM + c] = __float2half(v);
    sh0[r][c] = v;
    __syncthreads();
    // fused attention logits: 64 threads -> (4 rows x 16 outputs)
    if (tid < 64) {
        int rr = tid >> 4, o = tid & 15;
        int n = rb + rr;
        if (n < NN) {
            float s = 0.f;
#pragma unroll 8
            for (int k = 0; k < DIM; k++) s = fmaf(sh0[rr][k], sP[k * 16 + o], s);
            if (o < 8) g_as[n * 8 + o] = s;
            else       g_ad[n * 8 + (o - 8)] = s;
        }
    }
}

// ---------------- k_xh_mma: xh = h0h @ Wgh (fp16 HMMA, fp32 accum) -------------
#define XA_LD 72
#define XB_LD 136
__global__ void __launch_bounds__(256) k_xh_mma() {
    __shared__ __align__(16) char smem[64 * 128 * 4];
    __half* sA = (__half*)smem;
    __half* sB = (__half*)(smem + 64 * XA_LD * 2);
    float*  sC = (float*)smem;

    int tid = threadIdx.x;
    int warp = tid >> 5;
    int rb = blockIdx.x * 64;
    int cb = blockIdx.y * 128;

    for (int i = tid; i < 512; i += 256) {
        int row = i >> 3, c8 = i & 7;
        *(int4*)&sA[row * XA_LD + c8 * 8] =
            *(const int4*)&g_h0h[(size_t)(rb + row) * DIM + c8 * 8];
    }
    for (int i = tid; i < 1024; i += 256) {
        int row = i >> 4, c8 = i & 15;
        *(int4*)&sB[row * XB_LD + c8 * 8] =
            *(const int4*)&g_Wgh[row * F512 + cb + c8 * 8];
    }
    __syncthreads();

    int wm = warp & 3, wn = warp >> 2;
    wmma::fragment<wmma::accumulator, 16, 16, 16, float> acc[4];
#pragma unroll
    for (int n = 0; n < 4; n++) wmma::fill_fragment(acc[n], 0.f);

#pragma unroll
    for (int k = 0; k < 4; k++) {
        wmma::fragment<wmma::matrix_a, 16, 16, 16, __half, wmma::row_major> af;
        wmma::load_matrix_sync(af, &sA[(wm * 16) * XA_LD + k * 16], XA_LD);
#pragma unroll
        for (int n = 0; n < 4; n++) {
            wmma::fragment<wmma::matrix_b, 16, 16, 16, __half, wmma::row_major> bf;
            wmma::load_matrix_sync(bf, &sB[(k * 16) * XB_LD + wn * 64 + n * 16], XB_LD);
            wmma::mma_sync(acc[n], af, bf, acc[n]);
        }
    }
    __syncthreads();
#pragma unroll
    for (int n = 0; n < 4; n++)
        wmma::store_matrix_sync(&sC[(wm * 16) * 128 + wn * 64 + n * 16], acc[n], 128,
                                wmma::mem_row_major);
    __syncthreads();

    for (int i = tid; i < 64 * 64; i += 256) {
        int row = i >> 6, c2 = i & 63;
        float2 v = *(const float2*)&sC[row * 128 + 2 * c2];
        g_xh2[(size_t)(rb + row) * (F512 / 2) + (cb >> 1) + c2] = __floats2half2_rn(v.x, v.y);
    }
}

// ---------------- CSR build ----------------
__global__ void k_hist(const int* __restrict__ ei) {
    int e = blockIdx.x * 256 + threadIdx.x;
    if (e < EE) atomicAdd(&g_cnt[ei[EE + e]], 1);
}
__global__ void k_scan() {  // 1 block, 1024 threads
    __shared__ int partials[1024];
    int t = threadIdx.x;
    const int CH = 20;
    int base = t * CH;
    int local[CH];
    int s = 0;
#pragma unroll
    for (int u = 0; u < CH; u++) {
        int idx = base + u;
        int v = (idx < NN) ? g_cnt[idx] : 0;
        local[u] = s;
        s += v;
    }
    partials[t] = s;
    __syncthreads();
    for (int o = 1; o < 1024; o <<= 1) {
        int v = (t >= o) ? partials[t - o] : 0;
        __syncthreads();
        partials[t] += v;
        __syncthreads();
    }
    int pre = (t > 0) ? partials[t - 1] : 0;
#pragma unroll
    for (int u = 0; u < CH; u++) {
        int idx = base + u;
        if (idx < NN) {
            int o = pre + local[u];
            g_offs[idx] = o;
            g_cursor[idx] = o;
        }
    }
    if (t == 1023) g_offs[NN] = partials[1023];
}
__global__ void k_scatter(const int* __restrict__ ei) {
    int e = blockIdx.x * 256 + threadIdx.x;
    if (e < EE) {
        int d = ei[EE + e];
        int p = atomicAdd(&g_cursor[d], 1);
        g_csr[p] = ei[e];
    }
}

// ---------------- k4: GAT aggregation, warp/node, 2-edge unrolled --------------
__global__ void __launch_bounds__(256) k_agg(const float* __restrict__ bg) {
    int n = (blockIdx.x * blockDim.x + threadIdx.x) >> 5;
    int lane = threadIdx.x & 31;
    if (n >= NN) return;
    int s0 = g_offs[n], s1 = g_offs[n + 1];
    int hh = lane & 7;
    float adh = g_ad[n * 8 + hh];

    // ---- pass 1: per-head max ----
    float m = -INFINITY;
    if (lane < 8) m = lrelu(g_as[n * 8 + lane] + adh);  // self-loop
    {
        int i = s0 + (lane >> 3);
        int src = (i < s1) ? g_csr[i] : -1;
        while (i < s1) {
            int inext = i + 4;
            int srcn = (inext < s1) ? g_csr[inext] : -1;
            float e = lrelu(g_as[src * 8 + hh] + adh);
            m = fmaxf(m, e);
            src = srcn;
            i = inext;
        }
    }
    m = fmaxf(m, __shfl_xor_sync(0xffffffffu, m, 8));
    m = fmaxf(m, __shfl_xor_sync(0xffffffffu, m, 16));

    // ---- pass 2: weighted accumulate, 2 edges per iteration ----
    // edge t: src = (t==0) ? n : csr[s0+t-1]; total = cnt+1
    int total = (s1 - s0) + 1;
    float acc0[8], acc1[8];
#pragma unroll
    for (int t = 0; t < 8; t++) { acc0[t] = 0.f; acc1[t] = 0.f; }
    float ssum = 0.f;
    int head0 = lane >> 3;
    int head1 = (lane + 32) >> 3;

    int srcA = n;                                        // t = 0
    int srcB = (s0 < s1) ? g_csr[s0] : 0;                // t = 1
    for (int t = 0; t < total; t += 2) {
        int sA = srcA, sB = srcB;
        bool hasB = (t + 1 < total);
        // prefetch t+2, t+3
        srcA = (s0 + t + 1 < s1) ? g_csr[s0 + t + 1] : 0;
        srcB = (s0 + t + 2 < s1) ? g_csr[s0 + t + 2] : 0;

        const int4* rowA = (const int4*)(g_xh2 + (size_t)sA * (F512 / 2));
        const int4* rowB = (const int4*)(g_xh2 + (size_t)sB * (F512 / 2));
        int4 a0 = rowA[lane];
        int4 a1 = rowA[lane + 32];
        int4 b0 = rowB[lane];
        int4 b1 = rowB[lane + 32];

        float w = 0.f;
        if (lane < 16) {
            int es = (lane < 8) ? sA : sB;
            bool valid = (lane < 8) | hasB;
            if (valid) {
                float e = lrelu(g_as[es * 8 + hh] + adh);
                w = __expf(e - m);
            }
            ssum += w;
        }
        float wA0 = __shfl_sync(0xffffffffu, w, head0);
        float wA1 = __shfl_sync(0xffffffffu, w, head1);
        float wB0 = __shfl_sync(0xffffffffu, w, 8 + head0);
        float wB1 = __shfl_sync(0xffffffffu, w, 8 + head1);

        const __half2* pa0 = (const __half2*)&a0;
        const __half2* pa1 = (const __half2*)&a1;
        const __half2* pb0 = (const __half2*)&b0;
        const __half2* pb1 = (const __half2*)&b1;
#pragma unroll
        for (int q = 0; q < 4; q++) {
            float2 fa0 = __half22float2(pa0[q]);
            float2 fa1 = __half22float2(pa1[q]);
            float2 fb0 = __half22float2(pb0[q]);
            float2 fb1 = __half22float2(pb1[q]);
            acc0[2 * q]     = fmaf(wA0, fa0.x, acc0[2 * q]);
            acc0[2 * q + 1] = fmaf(wA0, fa0.y, acc0[2 * q + 1]);
            acc1[2 * q]     = fmaf(wA1, fa1.x, acc1[2 * q]);
            acc1[2 * q + 1] = fmaf(wA1, fa1.y, acc1[2 * q + 1]);
            acc0[2 * q]     = fmaf(wB0, fb0.x, acc0[2 * q]);
            acc0[2 * q + 1] = fmaf(wB0, fb0.y, acc0[2 * q + 1]);
            acc1[2 * q]     = fmaf(wB1, fb1.x, acc1[2 * q]);
            acc1[2 * q + 1] = fmaf(wB1, fb1.y, acc1[2 * q + 1]);
        }
    }
    // per-head sums: lanes {h, h+8, h+16, h+24} -> xor 8 + xor 16
    ssum += __shfl_xor_sync(0xffffffffu, ssum, 8);
    ssum += __shfl_xor_sync(0xffffffffu, ssum, 16);

    float sj0 = __shfl_sync(0xffffffffu, ssum, head0);
    float sj1 = __shfl_sync(0xffffffffu, ssum, head1);
    float inv0 = 1.0f / sj0, inv1 = 1.0f / sj1;
    {
        int ch = 8 * lane;
        float4 c0 = __ldg((const float4*)&bg[ch]);
        float4 c1 = __ldg((const float4*)&bg[ch + 4]);
        __half2 o[4];
        o[0] = __floats2half2_rn(fmaxf(acc0[0] * inv0 + c0.x, 0.f), fmaxf(acc0[1] * inv0 + c0.y, 0.f));
        o[1] = __floats2half2_rn(fmaxf(acc0[2] * inv0 + c0.z, 0.f), fmaxf(acc0[3] * inv0 + c0.w, 0.f));
        o[2] = __floats2half2_rn(fmaxf(acc0[4] * inv0 + c1.x, 0.f), fmaxf(acc0[5] * inv0 + c1.y, 0.f));
        o[3] = __floats2half2_rn(fmaxf(acc0[6] * inv0 + c1.z, 0.f), fmaxf(acc0[7] * inv0 + c1.w, 0.f));
        *(int4*)&g_aggh[(size_t)n * F512 + ch] = *(int4*)o;
    }
    {
        int ch = 8 * (lane + 32);
        float4 c0 = __ldg((const float4*)&bg[ch]);
        float4 c1 = __ldg((const float4*)&bg[ch + 4]);
        __half2 o[4];
        o[0] = __floats2half2_rn(fmaxf(acc1[0] * inv1 + c0.x, 0.f), fmaxf(acc1[1] * inv1 + c0.y, 0.f));
        o[1] = __floats2half2_rn(fmaxf(acc1[2] * inv1 + c0.z, 0.f), fmaxf(acc1[3] * inv1 + c0.w, 0.f));
        o[2] = __floats2half2_rn(fmaxf(acc1[4] * inv1 + c1.x, 0.f), fmaxf(acc1[5] * inv1 + c1.y, 0.f));
        o[3] = __floats2half2_rn(fmaxf(acc1[6] * inv1 + c1.z, 0.f), fmaxf(acc1[7] * inv1 + c1.w, 0.f));
        *(int4*)&g_aggh[(size_t)n * F512 + ch] = *(int4*)o;
    }
}

// ---------------- k_out_mma: out = relu(aggh @ Whh + bh) (HMMA) ----------------
#define OA_LD 72
#define OB_LD 72
__global__ void __launch_bounds__(256) k_out_mma(const float* __restrict__ bh) {
    __shared__ __align__(16) char smem[128 * 64 * 4];
    __half* sA = (__half*)smem;
    __half* sB = (__half*)(smem + 128 * OA_LD * 2);
    float*  sC = (float*)smem;

    int tid = threadIdx.x;
    int warp = tid >> 5;
    int rb = blockIdx.x * 128;

    wmma::fragment<wmma::accumulator, 16, 16, 16, float> acc[4];
#pragma unroll
    for (int n = 0; n < 4; n++) wmma::fill_fragment(acc[n], 0.f);

    for (int kc = 0; kc < 8; kc++) {
        for (int i = tid; i < 1024; i += 256) {
            int row = i >> 3, c8 = i & 7;
            *(int4*)&sA[row * OA_LD + c8 * 8] =
                *(const int4*)&g_aggh[(size_t)(rb + row) * F512 + kc * 64 + c8 * 8];
        }
        for (int i = tid; i < 512; i += 256) {
            int row = i >> 3, c8 = i & 7;
            *(int4*)&sB[row * OB_LD + c8 * 8] =
                *(const int4*)&g_Whh[(kc * 64 + row) * DIM + c8 * 8];
        }
        __syncthreads();
#pragma unroll
        for (int k = 0; k < 4; k++) {
            wmma::fragment<wmma::matrix_a, 16, 16, 16, __half, wmma::row_major> af;
            wmma::load_matrix_sync(af, &sA[(warp * 16) * OA_LD + k * 16], OA_LD);
#pragma unroll
            for (int n = 0; n < 4; n++) {
                wmma::fragment<wmma::matrix_b, 16, 16, 16, __half, wmma::row_major> bf;
                wmma::load_matrix_sync(bf, &sB[(k * 16) * OB_LD + n * 16], OB_LD);
                wmma::mma_sync(acc[n], af, bf, acc[n]);
            }
        }
        __syncthreads();
    }
#pragma unroll
    for (int n = 0; n < 4; n++)
        wmma::store_matrix_sync(&sC[(warp * 16) * 64 + n * 16], acc[n], 64,
                                wmma::mem_row_major);
    __syncthreads();

    for (int i = tid; i < 128 * 16; i += 256) {
        int row = i >> 4, c4 = i & 15;
        float4 v = *(const float4*)&sC[row * 64 + c4 * 4];
        float4 b = __ldg((const float4*)&bh[c4 * 4]);
        v.x = fmaxf(v.x + b.x, 0.f);
        v.y = fmaxf(v.y + b.y, 0.f);
        v.z = fmaxf(v.z + b.z, 0.f);
        v.w = fmaxf(v.w + b.w, 0.f);
        *(float4*)&g_out[(size_t)(rb + row) * DIM + c4 * 4] = v;
    }
}

// ---------------- k6: Set2Set (3 steps) + final MLP; one block per graph -------
__global__ void __launch_bounds__(256) k_s2s(
    const int* __restrict__ batch, const float* __restrict__ W_ih,
    const float* __restrict__ W_hh, const float* __restrict__ b_ih,
    const float* __restrict__ b_hh, const float* __restrict__ W1,
    const float* __restrict__ b1, const float* __restrict__ W2,
    const float* __restrict__ b2, float* __restrict__ y) {
    int b = blockIdx.x;
    int tid = threadIdx.x, lane = tid & 31, wid = tid >> 5;
    __shared__ float qs[128], hhv[64], ccv[64], gg[256];
    __shared__ float red[8][64];
    __shared__ float sred[8], mw[8];
    __shared__ float mfin_s;
    __shared__ int seg[2];
    if (tid == 0) {
        int lo = 0, hi = NN;
        while (lo < hi) { int mid = (lo + hi) >> 1; if (batch[mid] < b) lo = mid + 1; else hi = mid; }
        seg[0] = lo;
        hi = NN;
        while (lo < hi) { int mid = (lo + hi) >> 1; if (batch[mid] < b + 1) lo = mid + 1; else hi = mid; }
        seg[1] = lo;
    }
    if (tid < 128) qs[tid] = 0.f;
    if (tid < 64) { hhv[tid] = 0.f; ccv[tid] = 0.f; }
    __syncthreads();
    int s0 = seg[0], s1 = seg[1];

    for (int it = 0; it < 3; ++it) {
        float g = b_ih[tid] + b_hh[tid];
        const float* wi = W_ih + tid * 128;
#pragma unroll 4
        for (int k = 0; k < 128; k++) g = fmaf(qs[k], wi[k], g);
        const float* wh = W_hh + tid * 64;
#pragma unroll 4
        for (int k = 0; k < 64; k++) g = fmaf(hhv[k], wh[k], g);
        gg[tid] = g;
        __syncthreads();
        if (tid < 64) {
            float ig = gg[tid], fg = gg[64 + tid], gv = gg[128 + tid], og = gg[192 + tid];
            float c = sigmoidf_(fg) * ccv[tid] + sigmoidf_(ig) * tanhf(gv);
            ccv[tid] = c;
            hhv[tid] = sigmoidf_(og) * tanhf(c);
        }
        __syncthreads();

        float q0 = hhv[lane], q1 = hhv[lane + 32];
        float wmax = -INFINITY;
        for (int i = s0 + wid; i < s1; i += 8) {
            const float* o = g_out + (size_t)i * 64;
            float v = o[lane] * q0 + o[lane + 32] * q1;
#pragma unroll
            for (int off = 16; off; off >>= 1) v += __shfl_xor_sync(0xffffffffu, v, off);
            wmax = fmaxf(wmax, v);
        }
        if (lane == 0) mw[wid] = wmax;
        __syncthreads();
        if (tid == 0) {
            float m = -INFINITY;
#pragma unroll
            for (int w = 0; w < 8; w++) m = fmaxf(m, mw[w]);
            mfin_s = m;
        }
        __syncthreads();
        float m = mfin_s;
        float r0a = 0.f, r1a = 0.f, sl = 0.f;
        for (int i = s0 + wid; i < s1; i += 8) {
            const float* o = g_out + (size_t)i * 64;
            float a0 = o[lane], a1 = o[lane + 32];
            float v = a0 * q0 + a1 * q1;
#pragma unroll
            for (int off = 16; off; off >>= 1) v += __shfl_xor_sync(0xffffffffu, v, off);
            float w = __expf(v - m);
            sl += w;
            r0a = fmaf(w, a0, r0a);
            r1a = fmaf(w, a1, r1a);
        }
        red[wid][lane] = r0a;
        red[wid][lane + 32] = r1a;
        if (lane == 0) sred[wid] = sl;
        __syncthreads();
        if (tid < 64) {
            float s = 0.f, r = 0.f;
#pragma unroll
            for (int w = 0; w < 8; w++) { s += sred[w]; r += red[w][tid]; }
            float inv = (s > 0.f) ? 1.0f / s : 0.f;
            qs[tid] = hhv[tid];
            qs[64 + tid] = r * inv;
        }
        __syncthreads();
    }

    if (tid < 64) {
        float z = b1[tid];
#pragma unroll 4
        for (int k = 0; k < 128; k++) z = fmaf(qs[k], W1[k * 64 + tid], z);
        gg[tid] = fmaxf(z, 0.f);
    }
    __syncthreads();
    if (tid < 32) {
        float p = gg[tid] * W2[tid] + gg[tid + 32] * W2[tid + 32];
#pragma unroll
        for (int off = 16; off; off >>= 1) p += __shfl_xor_sync(0xffffffffu, p, off);
        if (tid == 0) y[b] = p + b2[0];
    }
}

// ---------------- launch (single stream) ----------------
extern "C" void kernel_launch(void* const* d_in, const int* in_sizes, int n_in,
                              void* d_out, int out_size) {
    const float* x       = (const float*)d_in[0];
    const int*   ei      = (const int*)d_in[1];   // [2,E] int32
    const int*   batch   = (const int*)d_in[2];
    const float* W0      = (const float*)d_in[3];
    const float* b0      = (const float*)d_in[4];
    const float* Wg      = (const float*)d_in[5];
    const float* att_src = (const float*)d_in[6];
    const float* att_dst = (const float*)d_in[7];
    const float* bg      = (const float*)d_in[8];
    const float* Wh      = (const float*)d_in[9];
    const float* bh      = (const float*)d_in[10];
    const float* W_ih    = (const float*)d_in[11];
    const float* W_hh    = (const float*)d_in[12];
    const float* b_ih    = (const float*)d_in[13];
    const float* b_hh    = (const float*)d_in[14];
    const float* W1      = (const float*)d_in[15];
    const float* b1      = (const float*)d_in[16];
    const float* W2      = (const float*)d_in[17];
    const float* b2      = (const float*)d_in[18];
    float* y = (float*)d_out;

    k_pre<<<128 + 79 + 1, 256>>>(Wg, Wh, att_src, att_dst);
    k_h0<<<NP / 4, 256>>>(x, W0, b0);
    k_xh_mma<<<dim3(NP / 64, 4), 256>>>();
    k_hist<<<(EE + 255) / 256, 256>>>(ei);
    k_scan<<<1, 1024>>>();
    k_scatter<<<(EE + 255) / 256, 256>>>(ei);
    k_agg<<<NN / 8, 256>>>(bg);
    k_out_mma<<<NP / 128, 256>>>(bh);
    k_s2s<<<BBATCH, 256>>>(batch, W_ih, W_hh, b_ih, b_hh, W1, b1, W2, b2, y);
}

// round 15
// speedup vs baseline: 1.6792x; 1.6792x over previous
#include <cuda_runtime.h>
#include <cuda_fp16.h>
#include <mma.h>
#include <math.h>

using namespace nvcuda;

#define NN   20000
#define NP   20096   // padded rows: 157*128
#define EE   320000
#define BBATCH 128
#define FIN  25
#define DIM  64
#define NH   8
#define F512 512   // NH*DIM

// ---------------- scratch (static device globals; zero-init, no allocation) ----
__device__ float   g_h0[NP * DIM];
__device__ __half  g_h0h[NP * DIM];
__device__ __half  g_Wgh[DIM * F512];
__device__ __half  g_Whh[F512 * DIM];
__device__ __half2 g_xh2[NP * (F512 / 2)];   // xh fp16
__device__ __half  g_aggh[NP * F512];        // agg fp16
__device__ float   g_P[DIM * 16];
__device__ float   g_as[NN * NH];
__device__ float   g_ad[NN * NH];
__device__ int     g_cnt[NN];
__device__ int     g_offs[NN + 1];
__device__ int     g_cursor[NN];
__device__ int     g_csr[EE];
__device__ float   g_out[NP * DIM];

__device__ __forceinline__ float lrelu(float x) { return x > 0.f ? x : 0.2f * x; }
__device__ __forceinline__ float sigmoidf_(float x) { return 1.f / (1.f + __expf(-x)); }

// ---------------- k_patt: P[k][o] = sum_c Wg[k,64h+c]*att[h,c] (1 block) -------
__global__ void k_patt(const float* __restrict__ Wg, const float* __restrict__ as_,
                       const float* __restrict__ ad_) {
    int k = threadIdx.x >> 4, o = threadIdx.x & 15;
    int h = o & 7;
    const float* att = (o < 8) ? as_ : ad_;
    float s = 0.f;
#pragma unroll 8
    for (int c = 0; c < 64; c++)
        s = fmaf(Wg[k * F512 + h * 64 + c], att[h * 64 + c], s);
    g_P[k * 16 + o] = s;
}

// ---------------- weight conversion to fp16 ----------------
__global__ void k_cvtW(const float* __restrict__ Wg, const float* __restrict__ Wh) {
    int i = blockIdx.x * 256 + threadIdx.x;
    if (i < DIM * F512) g_Wgh[i] = __float2half(Wg[i]);
    if (i < F512 * DIM) g_Whh[i] = __float2half(Wh[i]);
}

// ---------------- k1: h0 = relu(x @ W0 + b0) + fused a_s/a_d -------------------
__global__ void k_h0(const float* __restrict__ x, const float* __restrict__ W0,
                     const float* __restrict__ b0) {
    __shared__ float sW[FIN * DIM];
    __shared__ float sb[DIM];
    __shared__ float sx[4][FIN];
    __shared__ float sh0[4][DIM];
    __shared__ float sP[DIM * 16];
    int tid = threadIdx.x;
    for (int i = tid; i < FIN * DIM; i += 256) sW[i] = W0[i];
    for (int i = tid; i < DIM * 16; i += 256) sP[i] = g_P[i];
    if (tid < DIM) sb[tid] = b0[tid];
    int rb = blockIdx.x * 4;
    if (tid < 4 * FIN) {
        int row = rb + tid / FIN;
        sx[tid / FIN][tid % FIN] = (row < NN) ? x[(size_t)row * FIN + tid % FIN] : 0.f;
    }
    __syncthreads();
    int c = tid & 63, r = tid >> 6;
    float acc = sb[c];
#pragma unroll
    for (int k = 0; k < FIN; k++) acc = fmaf(sx[r][k], sW[k * DIM + c], acc);
    float v = fmaxf(acc, 0.f);
    g_h0[(size_t)(rb + r) * DIM + c] = v;
    g_h0h[(size_t)(rb + r) * DIM + c] = __float2half(v);
    sh0[r][c] = v;
    __syncthreads();
    // fused attention logits: 64 threads -> (4 rows x 16 outputs)
    if (tid < 64) {
        int rr = tid >> 4, o = tid & 15;
        int n = rb + rr;
        if (n < NN) {
            float s = 0.f;
#pragma unroll 8
            for (int k = 0; k < DIM; k++) s = fmaf(sh0[rr][k], sP[k * 16 + o], s);
            if (o < 8) g_as[n * 8 + o] = s;
            else       g_ad[n * 8 + (o - 8)] = s;
        }
    }
}

// ---------------- k_xh_mma: xh = h0h @ Wgh (fp16 HMMA, fp32 accum) -------------
#define XA_LD 72
#define XB_LD 136
__global__ void __launch_bounds__(256) k_xh_mma() {
    __shared__ __align__(16) char smem[64 * 128 * 4];
    __half* sA = (__half*)smem;
    __half* sB = (__half*)(smem + 64 * XA_LD * 2);
    float*  sC = (float*)smem;

    int tid = threadIdx.x;
    int warp = tid >> 5;
    int rb = blockIdx.x * 64;
    int cb = blockIdx.y * 128;

    for (int i = tid; i < 512; i += 256) {
        int row = i >> 3, c8 = i & 7;
        *(int4*)&sA[row * XA_LD + c8 * 8] =
            *(const int4*)&g_h0h[(size_t)(rb + row) * DIM + c8 * 8];
    }
    for (int i = tid; i < 1024; i += 256) {
        int row = i >> 4, c8 = i & 15;
        *(int4*)&sB[row * XB_LD + c8 * 8] =
            *(const int4*)&g_Wgh[row * F512 + cb + c8 * 8];
    }
    __syncthreads();

    int wm = warp & 3, wn = warp >> 2;
    wmma::fragment<wmma::accumulator, 16, 16, 16, float> acc[4];
#pragma unroll
    for (int n = 0; n < 4; n++) wmma::fill_fragment(acc[n], 0.f);

#pragma unroll
    for (int k = 0; k < 4; k++) {
        wmma::fragment<wmma::matrix_a, 16, 16, 16, __half, wmma::row_major> af;
        wmma::load_matrix_sync(af, &sA[(wm * 16) * XA_LD + k * 16], XA_LD);
#pragma unroll
        for (int n = 0; n < 4; n++) {
            wmma::fragment<wmma::matrix_b, 16, 16, 16, __half, wmma::row_major> bf;
            wmma::load_matrix_sync(bf, &sB[(k * 16) * XB_LD + wn * 64 + n * 16], XB_LD);
            wmma::mma_sync(acc[n], af, bf, acc[n]);
        }
    }
    __syncthreads();
#pragma unroll
    for (int n = 0; n < 4; n++)
        wmma::store_matrix_sync(&sC[(wm * 16) * 128 + wn * 64 + n * 16], acc[n], 128,
                                wmma::mem_row_major);
    __syncthreads();

    for (int i = tid; i < 64 * 64; i += 256) {
        int row = i >> 6, c2 = i & 63;
        float2 v = *(const float2*)&sC[row * 128 + 2 * c2];
        g_xh2[(size_t)(rb + row) * (F512 / 2) + (cb >> 1) + c2] = __floats2half2_rn(v.x, v.y);
    }
}

// ---------------- CSR build ----------------
__global__ void k_zero() {
    int i = blockIdx.x * 256 + threadIdx.x;
    if (i < NN) g_cnt[i] = 0;
}
__global__ void k_hist(const int* __restrict__ ei) {
    int e = blockIdx.x * 256 + threadIdx.x;
    if (e < EE) atomicAdd(&g_cnt[ei[EE + e]], 1);
}
__global__ void k_scan() {  // 1 block, 1024 threads
    __shared__ int partials[1024];
    int t = threadIdx.x;
    const int CH = 20;
    int base = t * CH;
    int local[CH];
    int s = 0;
#pragma unroll
    for (int u = 0; u < CH; u++) {
        int idx = base + u;
        int v = (idx < NN) ? g_cnt[idx] : 0;
        local[u] = s;
        s += v;
    }
    partials[t] = s;
    __syncthreads();
    for (int o = 1; o < 1024; o <<= 1) {
        int v = (t >= o) ? partials[t - o] : 0;
        __syncthreads();
        partials[t] += v;
        __syncthreads();
    }
    int pre = (t > 0) ? partials[t - 1] : 0;
#pragma unroll
    for (int u = 0; u < CH; u++) {
        int idx = base + u;
        if (idx < NN) {
            int o = pre + local[u];
            g_offs[idx] = o;
            g_cursor[idx] = o;
        }
    }
    if (t == 1023) g_offs[NN] = partials[1023];
}
__global__ void k_scatter(const int* __restrict__ ei) {
    int e = blockIdx.x * 256 + threadIdx.x;
    if (e < EE) {
        int d = ei[EE + e];
        int p = atomicAdd(&g_cursor[d], 1);
        g_csr[p] = ei[e];
    }
}

// ---------------- k4: GAT aggregation, warp per dst node (R10 1-edge loop) -----
__global__ void __launch_bounds__(256) k_agg(const float* __restrict__ bg) {
    int n = (blockIdx.x * blockDim.x + threadIdx.x) >> 5;
    int lane = threadIdx.x & 31;
    if (n >= NN) return;
    int s0 = g_offs[n], s1 = g_offs[n + 1];
    int hh = lane & 7;
    float adh = g_ad[n * 8 + hh];

    // ---- pass 1: per-head max ----
    float m = -INFINITY;
    if (lane < 8) m = lrelu(g_as[n * 8 + lane] + adh);  // self-loop
    {
        int i = s0 + (lane >> 3);
        int src = (i < s1) ? g_csr[i] : -1;
        while (i < s1) {
            int inext = i + 4;
            int srcn = (inext < s1) ? g_csr[inext] : -1;
            float e = lrelu(g_as[src * 8 + hh] + adh);
            m = fmaxf(m, e);
            src = srcn;
            i = inext;
        }
    }
    m = fmaxf(m, __shfl_xor_sync(0xffffffffu, m, 8));
    m = fmaxf(m, __shfl_xor_sync(0xffffffffu, m, 16));

    // ---- pass 2: weighted accumulate ----
    float acc0[8], acc1[8];
#pragma unroll
    for (int t = 0; t < 8; t++) { acc0[t] = 0.f; acc1[t] = 0.f; }
    float ssum = 0.f;
    int head0 = lane >> 3;
    int head1 = (lane + 32) >> 3;
    int src_cur = n;
    for (int i = s0 - 1; i < s1; ++i) {
        int inext = i + 1;
        int src_next = (inext < s1) ? g_csr[inext] : 0;
        const int4* row = (const int4*)(g_xh2 + (size_t)src_cur * (F512 / 2));
        int4 v0 = row[lane];
        int4 v1 = row[lane + 32];
        float w = 0.f;
        if (lane < 8) {
            float e = lrelu(g_as[src_cur * 8 + lane] + adh);
            w = __expf(e - m);
            ssum += w;
        }
        float wj0 = __shfl_sync(0xffffffffu, w, head0);
        float wj1 = __shfl_sync(0xffffffffu, w, head1);
        const __half2* hp0 = (const __half2*)&v0;
        const __half2* hp1 = (const __half2*)&v1;
#pragma unroll
        for (int t = 0; t < 4; t++) {
            float2 f0 = __half22float2(hp0[t]);
            float2 f1 = __half22float2(hp1[t]);
            acc0[2 * t]     = fmaf(wj0, f0.x, acc0[2 * t]);
            acc0[2 * t + 1] = fmaf(wj0, f0.y, acc0[2 * t + 1]);
            acc1[2 * t]     = fmaf(wj1, f1.x, acc1[2 * t]);
            acc1[2 * t + 1] = fmaf(wj1, f1.y, acc1[2 * t + 1]);
        }
        src_cur = src_next;
    }

    float sj0 = __shfl_sync(0xffffffffu, ssum, head0);
    float sj1 = __shfl_sync(0xffffffffu, ssum, head1);
    float inv0 = 1.0f / sj0, inv1 = 1.0f / sj1;
    {
        int ch = 8 * lane;
        float4 b0 = __ldg((const float4*)&bg[ch]);
        float4 b1 = __ldg((const float4*)&bg[ch + 4]);
        __half2 o[4];
        o[0] = __floats2half2_rn(fmaxf(acc0[0] * inv0 + b0.x, 0.f), fmaxf(acc0[1] * inv0 + b0.y, 0.f));
        o[1] = __floats2half2_rn(fmaxf(acc0[2] * inv0 + b0.z, 0.f), fmaxf(acc0[3] * inv0 + b0.w, 0.f));
        o[2] = __floats2half2_rn(fmaxf(acc0[4] * inv0 + b1.x, 0.f), fmaxf(acc0[5] * inv0 + b1.y, 0.f));
        o[3] = __floats2half2_rn(fmaxf(acc0[6] * inv0 + b1.z, 0.f), fmaxf(acc0[7] * inv0 + b1.w, 0.f));
        *(int4*)&g_aggh[(size_t)n * F512 + ch] = *(int4*)o;
    }
    {
        int ch = 8 * (lane + 32);
        float4 b0 = __ldg((const float4*)&bg[ch]);
        float4 b1 = __ldg((const float4*)&bg[ch + 4]);
        __half2 o[4];
        o[0] = __floats2half2_rn(fmaxf(acc1[0] * inv1 + b0.x, 0.f), fmaxf(acc1[1] * inv1 + b0.y, 0.f));
        o[1] = __floats2half2_rn(fmaxf(acc1[2] * inv1 + b0.z, 0.f), fmaxf(acc1[3] * inv1 + b0.w, 0.f));
        o[2] = __floats2half2_rn(fmaxf(acc1[4] * inv1 + b1.x, 0.f), fmaxf(acc1[5] * inv1 + b1.y, 0.f));
        o[3] = __floats2half2_rn(fmaxf(acc1[6] * inv1 + b1.z, 0.f), fmaxf(acc1[7] * inv1 + b1.w, 0.f));
        *(int4*)&g_aggh[(size_t)n * F512 + ch] = *(int4*)o;
    }
}

// ---------------- k_out_mma: out = relu(aggh @ Whh + bh) (HMMA) ----------------
#define OA_LD 72
#define OB_LD 72
__global__ void __launch_bounds__(256) k_out_mma(const float* __restrict__ bh) {
    __shared__ __align__(16) char smem[128 * 64 * 4];
    __half* sA = (__half*)smem;
    __half* sB = (__half*)(smem + 128 * OA_LD * 2);
    float*  sC = (float*)smem;

    int tid = threadIdx.x;
    int warp = tid >> 5;
    int rb = blockIdx.x * 128;

    wmma::fragment<wmma::accumulator, 16, 16, 16, float> acc[4];
#pragma unroll
    for (int n = 0; n < 4; n++) wmma::fill_fragment(acc[n], 0.f);

    for (int kc = 0; kc < 8; kc++) {
        for (int i = tid; i < 1024; i += 256) {
            int row = i >> 3, c8 = i & 7;
            *(int4*)&sA[row * OA_LD + c8 * 8] =
                *(const int4*)&g_aggh[(size_t)(rb + row) * F512 + kc * 64 + c8 * 8];
        }
        for (int i = tid; i < 512; i += 256) {
            int row = i >> 3, c8 = i & 7;
            *(int4*)&sB[row * OB_LD + c8 * 8] =
                *(const int4*)&g_Whh[(kc * 64 + row) * DIM + c8 * 8];
        }
        __syncthreads();
#pragma unroll
        for (int k = 0; k < 4; k++) {
            wmma::fragment<wmma::matrix_a, 16, 16, 16, __half, wmma::row_major> af;
            wmma::load_matrix_sync(af, &sA[(warp * 16) * OA_LD + k * 16], OA_LD);
#pragma unroll
            for (int n = 0; n < 4; n++) {
                wmma::fragment<wmma::matrix_b, 16, 16, 16, __half, wmma::row_major> bf;
                wmma::load_matrix_sync(bf, &sB[(k * 16) * OB_LD + n * 16], OB_LD);
                wmma::mma_sync(acc[n], af, bf, acc[n]);
            }
        }
        __syncthreads();
    }
#pragma unroll
    for (int n = 0; n < 4; n++)
        wmma::store_matrix_sync(&sC[(warp * 16) * 64 + n * 16], acc[n], 64,
                                wmma::mem_row_major);
    __syncthreads();

    for (int i = tid; i < 128 * 16; i += 256) {
        int row = i >> 4, c4 = i & 15;
        float4 v = *(const float4*)&sC[row * 64 + c4 * 4];
        float4 b = __ldg((const float4*)&bh[c4 * 4]);
        v.x = fmaxf(v.x + b.x, 0.f);
        v.y = fmaxf(v.y + b.y, 0.f);
        v.z = fmaxf(v.z + b.z, 0.f);
        v.w = fmaxf(v.w + b.w, 0.f);
        *(float4*)&g_out[(size_t)(rb + row) * DIM + c4 * 4] = v;
    }
}

// ---------------- k6: Set2Set (3 steps) + final MLP; one block per graph -------
__global__ void __launch_bounds__(256) k_s2s(
    const int* __restrict__ batch, const float* __restrict__ W_ih,
    const float* __restrict__ W_hh, const float* __restrict__ b_ih,
    const float* __restrict__ b_hh, const float* __restrict__ W1,
    const float* __restrict__ b1, const float* __restrict__ W2,
    const float* __restrict__ b2, float* __restrict__ y) {
    int b = blockIdx.x;
    int tid = threadIdx.x, lane = tid & 31, wid = tid >> 5;
    __shared__ float qs[128], hhv[64], ccv[64], gg[256];
    __shared__ float red[8][64];
    __shared__ float sred[8], mw[8];
    __shared__ float mfin_s;
    __shared__ int seg[2];
    if (tid == 0) {
        int lo = 0, hi = NN;
        while (lo < hi) { int mid = (lo + hi) >> 1; if (batch[mid] < b) lo = mid + 1; else hi = mid; }
        seg[0] = lo;
        hi = NN;
        while (lo < hi) { int mid = (lo + hi) >> 1; if (batch[mid] < b + 1) lo = mid + 1; else hi = mid; }
        seg[1] = lo;
    }
    if (tid < 128) qs[tid] = 0.f;
    if (tid < 64) { hhv[tid] = 0.f; ccv[tid] = 0.f; }
    __syncthreads();
    int s0 = seg[0], s1 = seg[1];

    for (int it = 0; it < 3; ++it) {
        float g = b_ih[tid] + b_hh[tid];
        const float* wi = W_ih + tid * 128;
#pragma unroll 4
        for (int k = 0; k < 128; k++) g = fmaf(qs[k], wi[k], g);
        const float* wh = W_hh + tid * 64;
#pragma unroll 4
        for (int k = 0; k < 64; k++) g = fmaf(hhv[k], wh[k], g);
        gg[tid] = g;
        __syncthreads();
        if (tid < 64) {
            float ig = gg[tid], fg = gg[64 + tid], gv = gg[128 + tid], og = gg[192 + tid];
            float c = sigmoidf_(fg) * ccv[tid] + sigmoidf_(ig) * tanhf(gv);
            ccv[tid] = c;
            hhv[tid] = sigmoidf_(og) * tanhf(c);
        }
        __syncthreads();

        float q0 = hhv[lane], q1 = hhv[lane + 32];
        float wmax = -INFINITY;
        for (int i = s0 + wid; i < s1; i += 8) {
            const float* o = g_out + (size_t)i * 64;
            float v = o[lane] * q0 + o[lane + 32] * q1;
#pragma unroll
            for (int off = 16; off; off >>= 1) v += __shfl_xor_sync(0xffffffffu, v, off);
            wmax = fmaxf(wmax, v);
        }
        if (lane == 0) mw[wid] = wmax;
        __syncthreads();
        if (tid == 0) {
            float m = -INFINITY;
#pragma unroll
            for (int w = 0; w < 8; w++) m = fmaxf(m, mw[w]);
            mfin_s = m;
        }
        __syncthreads();
        float m = mfin_s;
        float r0a = 0.f, r1a = 0.f, sl = 0.f;
        for (int i = s0 + wid; i < s1; i += 8) {
            const float* o = g_out + (size_t)i * 64;
            float a0 = o[lane], a1 = o[lane + 32];
            float v = a0 * q0 + a1 * q1;
#pragma unroll
            for (int off = 16; off; off >>= 1) v += __shfl_xor_sync(0xffffffffu, v, off);
            float w = __expf(v - m);
            sl += w;
            r0a = fmaf(w, a0, r0a);
            r1a = fmaf(w, a1, r1a);
        }
        red[wid][lane] = r0a;
        red[wid][lane + 32] = r1a;
        if (lane == 0) sred[wid] = sl;
        __syncthreads();
        if (tid < 64) {
            float s = 0.f, r = 0.f;
#pragma unroll
            for (int w = 0; w < 8; w++) { s += sred[w]; r += red[w][tid]; }
            float inv = (s > 0.f) ? 1.0f / s : 0.f;
            qs[tid] = hhv[tid];
            qs[64 + tid] = r * inv;
        }
        __syncthreads();
    }

    if (tid < 64) {
        float z = b1[tid];
#pragma unroll 4
        for (int k = 0; k < 128; k++) z = fmaf(qs[k], W1[k * 64 + tid], z);
        gg[tid] = fmaxf(z, 0.f);
    }
    __syncthreads();
    if (tid < 32) {
        float p = gg[tid] * W2[tid] + gg[tid + 32] * W2[tid + 32];
#pragma unroll
        for (int off = 16; off; off >>= 1) p += __shfl_xor_sync(0xffffffffu, p, off);
        if (tid == 0) y[b] = p + b2[0];
    }
}

// ---------------- launch (single stream) ----------------
extern "C" void kernel_launch(void* const* d_in, const int* in_sizes, int n_in,
                              void* d_out, int out_size) {
    const float* x       = (const float*)d_in[0];
    const int*   ei      = (const int*)d_in[1];   // [2,E] int32
    const int*   batch   = (const int*)d_in[2];
    const float* W0      = (const float*)d_in[3];
    const float* b0      = (const float*)d_in[4];
    const float* Wg      = (const float*)d_in[5];
    const float* att_src = (const float*)d_in[6];
    const float* att_dst = (const float*)d_in[7];
    const float* bg      = (const float*)d_in[8];
    const float* Wh      = (const float*)d_in[9];
    const float* bh      = (const float*)d_in[10];
    const float* W_ih    = (const float*)d_in[11];
    const float* W_hh    = (const float*)d_in[12];
    const float* b_ih    = (const float*)d_in[13];
    const float* b_hh    = (const float*)d_in[14];
    const float* W1      = (const float*)d_in[15];
    const float* b1      = (const float*)d_in[16];
    const float* W2      = (const float*)d_in[17];
    const float* b2      = (const float*)d_in[18];
    float* y = (float*)d_out;

    k_patt<<<1, 1024>>>(Wg, att_src, att_dst);
    k_cvtW<<<(DIM * F512 + 255) / 256, 256>>>(Wg, Wh);
    k_h0<<<NP / 4, 256>>>(x, W0, b0);
    k_xh_mma<<<dim3(NP / 64, 4), 256>>>();
    k_zero<<<(NN + 255) / 256, 256>>>();
    k_hist<<<(EE + 255) / 256, 256>>>(ei);
    k_scan<<<1, 1024>>>();
    k_scatter<<<(EE + 255) / 256, 256>>>(ei);
    k_agg<<<NN / 8, 256>>>(bg);
    k_out_mma<<<NP / 128, 256>>>(bh);
    k_s2s<<<BBATCH, 256>>>(batch, W_ih, W_hh, b_ih, b_hh, W1, b1, W2, b2, y);
}